// round 11
// baseline (speedup 1.0000x reference)
#include <cuda_runtime.h>
#include <cstdint>

#define FULL 0xFFFFFFFFu
#define LQ 32
#define MQ 32
#define CQ 96
#define SPW 2                  // samples per warp
#define SPB (8 * SPW)          // samples per block = 16
#define PADW 33
#define MAXB 8192

__device__ float2 g_pn[MAXB];
__device__ unsigned g_done;

__device__ __forceinline__ unsigned forder(float f) {
    unsigned u = __float_as_uint(f);
    return u ^ (unsigned)(((int)u >> 31) | 0x80000000);
}
__device__ __forceinline__ float ex2(float a) {
    float r; asm("ex2.approx.f32 %0, %1;" : "=f"(r) : "f"(a)); return r;
}

// warp 32x32 bit transpose: in = row mask of this lane, out = column mask
__device__ __forceinline__ unsigned bit_transpose(unsigned w, int lane) {
    unsigned yv;
    yv = __shfl_xor_sync(FULL, w, 16);
    w = (lane & 16) ? ((w & 0xFFFF0000u) | ((yv >> 16) & 0x0000FFFFu))
                    : ((w & 0x0000FFFFu) | ((yv & 0x0000FFFFu) << 16));
    yv = __shfl_xor_sync(FULL, w, 8);
    w = (lane & 8) ? ((w & 0xFF00FF00u) | ((yv >> 8) & 0x00FF00FFu))
                   : ((w & 0x00FF00FFu) | ((yv & 0x00FF00FFu) << 8));
    yv = __shfl_xor_sync(FULL, w, 4);
    w = (lane & 4) ? ((w & 0xF0F0F0F0u) | ((yv >> 4) & 0x0F0F0F0Fu))
                   : ((w & 0x0F0F0F0Fu) | ((yv & 0x0F0F0F0Fu) << 4));
    yv = __shfl_xor_sync(FULL, w, 2);
    w = (lane & 2) ? ((w & 0xCCCCCCCCu) | ((yv >> 2) & 0x33333333u))
                   : ((w & 0x33333333u) | ((yv & 0x33333333u) << 2));
    yv = __shfl_xor_sync(FULL, w, 1);
    w = (lane & 1) ? ((w & 0xAAAAAAAAu) | ((yv >> 1) & 0x55555555u))
                   : ((w & 0x55555555u) | ((yv & 0x55555555u) << 1));
    return w;
}

__global__ void __launch_bounds__(256, 4) editloss_main(
    const float* __restrict__ x, const int* __restrict__ y,
    float* __restrict__ out, int B, int nblocks)
{
    __shared__ unsigned sEq[SPB * PADW];
    __shared__ unsigned sDg[SPB * PADW];
    __shared__ unsigned sUp[SPB * PADW];
    __shared__ unsigned sPair[SPB * PADW];
    __shared__ int      sN[SPB];
    __shared__ float    ss[256], sc[256];
    __shared__ unsigned s_last;

    const int warp = threadIdx.x >> 5;
    const int lane = threadIdx.x & 31;

    float my_lse[SPW]; int my_pred[SPW]; int t_reg[SPW];

    // ============ Phase 1: softmax/argmax + Eq masks (warp, 2 samples) =====
    #pragma unroll
    for (int k = 0; k < SPW; ++k) {
        const int slot = warp * SPW + k;
        const int b = blockIdx.x * SPB + slot;
        my_lse[k] = 0.f; my_pred[k] = 0; t_reg[k] = 0;
        if (b >= B) { if (lane == 0) sN[slot] = 0; continue; }

        const float4* xb4 = (const float4*)(x + (size_t)b * (LQ * CQ));
        t_reg[k] = y[b * MQ + lane];

        #pragma unroll 4
        for (int r = 0; r < LQ; ++r) {
            float4 v = (lane < 24) ? xb4[r * 24 + lane]
                                   : make_float4(-1e30f, -1e30f, -1e30f, -1e30f);
            float m = v.x; int idx = 4 * lane;
            if (v.y > m) { m = v.y; idx = 4 * lane + 1; }
            if (v.z > m) { m = v.z; idx = 4 * lane + 2; }
            if (v.w > m) { m = v.w; idx = 4 * lane + 3; }
            unsigned fo = forder(m);
            unsigned wmax = __reduce_max_sync(FULL, fo);
            unsigned bal = __ballot_sync(FULL, fo == wmax);
            int widx = __shfl_sync(FULL, idx, __ffs((int)bal) - 1);
            float e0 = ex2(fmaf(v.x, 1.44269504f, 14.f));
            float e1 = ex2(fmaf(v.y, 1.44269504f, 14.f));
            float e2 = ex2(fmaf(v.z, 1.44269504f, 14.f));
            float e3 = ex2(fmaf(v.w, 1.44269504f, 14.f));
            int si = __float2int_rn((e0 + e1) + (e2 + e3));
            int stot = __reduce_add_sync(FULL, si);
            if (lane == r) {
                my_pred[k] = widx;
                my_lse[k] = __logf((float)stot) - 14.f * 0.69314718f;
            }
        }

        unsigned mmask = 0;
        #pragma unroll
        for (int o = 0; o < MQ; ++o) {
            int tc = __shfl_sync(FULL, t_reg[k], o);
            if (my_pred[k] == tc) mmask |= 1u << o;
        }
        sEq[slot * PADW + lane] = bit_transpose(mmask, lane);
    }
    __syncthreads();

    // ============ Phase 2+3: Myers DP + backtrace (16 threads) =============
    if (threadIdx.x < SPB) {
        const int s = threadIdx.x;
        if (blockIdx.x * SPB + s < B) {
            unsigned pv = 0xFFFFFFFFu, mv = 0u;
            #pragma unroll 4
            for (int j = 0; j < MQ; ++j) {
                unsigned eq  = sEq[s * PADW + j];
                unsigned xv  = eq | mv;
                unsigned xh  = (((eq & pv) + pv) ^ pv) | eq;
                unsigned ph  = mv | ~(xh | pv);
                unsigned mh  = pv & xh;
                unsigned phs = (ph << 1) | 1u;
                unsigned mhs = mh << 1;
                unsigned pv2 = mhs | ~(xv | phs);
                unsigned mv2 = phs & xv;
                unsigned dg = eq | (pv2 & ~phs & ~mhs) | (~pv2 & ~mv2 & phs);
                sDg[s * PADW + j] = dg;
                sUp[s * PADW + j] = pv2 & ~dg;
                pv = pv2; mv = mv2;
            }
            int ii = LQ, jj = MQ, n = 0;
            unsigned dg = sDg[s * PADW + jj - 1];
            unsigned up = sUp[s * PADW + jj - 1];
            while ((ii | jj) != 0) {
                int code;
                if (ii > 0 && jj > 0) {
                    unsigned bit = 1u << (ii - 1);
                    code = (dg & bit) ? 0 : ((up & bit) ? 1 : 2);
                } else code = (ii > 0) ? 1 : 2;
                if (code == 0) {
                    sPair[s * PADW + n] =
                        (unsigned)(ii - 1) | ((unsigned)(jj - 1) << 6);
                    ++n; --ii; --jj;
                    if (jj > 0) { dg = sDg[s*PADW+jj-1]; up = sUp[s*PADW+jj-1]; }
                } else if (code == 1) { --ii; }
                else { --jj;
                    if (jj > 0) { dg = sDg[s*PADW+jj-1]; up = sUp[s*PADW+jj-1]; }
                }
            }
            sN[s] = n;
        }
    }
    __syncthreads();

    // ============ Phase 4: CE over diagonal steps (warp, 2 samples) ========
    #pragma unroll
    for (int k = 0; k < SPW; ++k) {
        const int slot = warp * SPW + k;
        const int b = blockIdx.x * SPB + slot;
        if (b >= B) continue;
        int n = sN[slot];
        unsigned pr = sPair[slot * PADW + ((lane < n) ? lane : 0)];
        int xi = pr & 31;
        int yj = (pr >> 6) & 31;
        int lab = __shfl_sync(FULL, t_reg[k], yj);
        float lsev = __shfl_sync(FULL, my_lse[k], xi);
        float ce = 0.f;
        if (lane < n)
            ce = lsev - __ldg(x + (size_t)b * (LQ * CQ) + xi * CQ + lab);
        #pragma unroll
        for (int o = 16; o; o >>= 1) ce += __shfl_xor_sync(FULL, ce, o);
        if (lane == 0)
            g_pn[b] = make_float2((n > 0) ? ce / (float)n : 0.f,
                                  (n > 0) ? 1.f : 0.f);
    }

    // ============ fused final reduction (last block) ========================
    __syncthreads();
    if (threadIdx.x == 0) {
        __threadfence();
        unsigned t = atomicAdd(&g_done, 1u);
        s_last = (t == (unsigned)(nblocks - 1)) ? 1u : 0u;
    }
    __syncthreads();
    if (s_last) {
        __threadfence();
        const float4* p = (const float4*)g_pn;
        float s = 0.f, c = 0.f;
        int n4 = B >> 1;
        for (int idx = threadIdx.x; idx < n4; idx += 256) {
            float4 v = p[idx];
            s += v.x + v.z;
            c += v.y + v.w;
        }
        if ((B & 1) && threadIdx.x == 0) { float2 t2 = g_pn[B-1]; s += t2.x; c += t2.y; }
        ss[threadIdx.x] = s; sc[threadIdx.x] = c;
        __syncthreads();
        #pragma unroll
        for (int o = 128; o > 0; o >>= 1) {
            if ((int)threadIdx.x < o) {
                ss[threadIdx.x] += ss[threadIdx.x + o];
                sc[threadIdx.x] += sc[threadIdx.x + o];
            }
            __syncthreads();
        }
        if (threadIdx.x == 0) {
            out[0] = ss[0] / sc[0];
            g_done = 0;
        }
    }
}

extern "C" void kernel_launch(void* const* d_in, const int* in_sizes, int n_in,
                              void* d_out, int out_size)
{
    const float* x = (const float*)d_in[0];
    const int*   y = (const int*)d_in[1];
    int B = in_sizes[2];
    if (B > MAXB) B = MAXB;

    int blocks = (B + SPB - 1) / SPB;
    editloss_main<<<blocks, 256>>>(x, y, (float*)d_out, B, blocks);
}

// round 14
// speedup vs baseline: 1.1233x; 1.1233x over previous
#include <cuda_runtime.h>
#include <cstdint>

#define FULL 0xFFFFFFFFu
#define LQ 32
#define MQ 32
#define CQ 96
#define SPB 8
#define PADW 33
#define MAXB 8192

__device__ float2 g_pn[MAXB];
__device__ unsigned g_done;

__device__ __forceinline__ unsigned forder(float f) {
    unsigned u = __float_as_uint(f);
    return u ^ (unsigned)(((int)u >> 31) | 0x80000000);
}
__device__ __forceinline__ float ex2(float a) {
    float r; asm("ex2.approx.f32 %0, %1;" : "=f"(r) : "f"(a)); return r;
}

__global__ void __launch_bounds__(32 * SPB, 5) editloss_main(
    const float* __restrict__ x, const int* __restrict__ y,
    float* __restrict__ out, int B, int nblocks)
{
    __shared__ unsigned sEq[SPB * PADW];
    __shared__ unsigned sDg[SPB * PADW];
    __shared__ unsigned sUp[SPB * PADW];
    __shared__ unsigned sPair[SPB * PADW];
    __shared__ int      sN[SPB];
    __shared__ float    ss[32 * SPB], sc[32 * SPB];
    __shared__ unsigned s_last;

    const int warp = threadIdx.x >> 5;
    const int lane = threadIdx.x & 31;
    const int b = blockIdx.x * SPB + warp;
    const bool act = (b < B);

    float my_lse = 0.f; int my_pred = 0; int t_reg = 0;

    // ================= Phase 1: softmax/argmax + Eq masks ==================
    if (act) {
        const float4* xb4 = (const float4*)(x + (size_t)b * (LQ * CQ));
        t_reg = y[b * MQ + lane];
        const int ibase = 4 * lane;
        int my_stot = 1;   // guards log(0); real rows always overwrite

        #pragma unroll 4
        for (int r = 0; r < LQ; ++r) {
            float4 v = (lane < 24) ? xb4[r * 24 + lane]
                                   : make_float4(-1e30f, -1e30f, -1e30f, -1e30f);
            float m = v.x; int idx = ibase;
            if (v.y > m) { m = v.y; idx = ibase + 1; }
            if (v.z > m) { m = v.z; idx = ibase + 2; }
            if (v.w > m) { m = v.w; idx = ibase + 3; }
            unsigned fo = forder(m);
            unsigned wmax = __reduce_max_sync(FULL, fo);
            unsigned cand = (fo == wmax) ? (unsigned)idx : 1023u;
            int widx = (int)__reduce_min_sync(FULL, cand);
            // sum of exp(v)*2^14 via ex2(v*log2e + 14), fixed-point warp add
            float e0 = ex2(fmaf(v.x, 1.44269504f, 14.f));
            float e1 = ex2(fmaf(v.y, 1.44269504f, 14.f));
            float e2 = ex2(fmaf(v.z, 1.44269504f, 14.f));
            float e3 = ex2(fmaf(v.w, 1.44269504f, 14.f));
            int si = __float2int_rn((e0 + e1) + (e2 + e3));
            int stot = __reduce_add_sync(FULL, si);
            if (lane == r) { my_pred = widx; my_stot = stot; }
        }
        // log once, outside the row loop
        my_lse = __logf((float)my_stot) - 14.f * 0.69314718f;

        // match mask: lane = row r, bit j = (pred_r == tgt_j)
        unsigned mmask = 0;
        #pragma unroll
        for (int o = 0; o < MQ; ++o) {
            int tc = __shfl_sync(FULL, t_reg, o);
            if (my_pred == tc) mmask |= 1u << o;
        }
        // warp 32x32 bit transpose -> lane j holds Eq_j (bits over rows)
        unsigned w = mmask;
        {
            unsigned yv;
            yv = __shfl_xor_sync(FULL, w, 16);
            w = (lane & 16) ? ((w & 0xFFFF0000u) | ((yv >> 16) & 0x0000FFFFu))
                            : ((w & 0x0000FFFFu) | ((yv & 0x0000FFFFu) << 16));
            yv = __shfl_xor_sync(FULL, w, 8);
            w = (lane & 8) ? ((w & 0xFF00FF00u) | ((yv >> 8) & 0x00FF00FFu))
                           : ((w & 0x00FF00FFu) | ((yv & 0x00FF00FFu) << 8));
            yv = __shfl_xor_sync(FULL, w, 4);
            w = (lane & 4) ? ((w & 0xF0F0F0F0u) | ((yv >> 4) & 0x0F0F0F0Fu))
                           : ((w & 0x0F0F0F0Fu) | ((yv & 0x0F0F0F0Fu) << 4));
            yv = __shfl_xor_sync(FULL, w, 2);
            w = (lane & 2) ? ((w & 0xCCCCCCCCu) | ((yv >> 2) & 0x33333333u))
                           : ((w & 0x33333333u) | ((yv & 0x33333333u) << 2));
            yv = __shfl_xor_sync(FULL, w, 1);
            w = (lane & 1) ? ((w & 0xAAAAAAAAu) | ((yv >> 1) & 0x55555555u))
                           : ((w & 0x55555555u) | ((yv & 0x55555555u) << 1));
        }
        sEq[warp * PADW + lane] = w;
    }
    __syncthreads();

    // ============ Phase 2+3: Myers bit-parallel DP + backtrace =============
    if (threadIdx.x < SPB) {
        const int s = threadIdx.x;
        if (blockIdx.x * SPB + s < B) {
            unsigned pv = 0xFFFFFFFFu, mv = 0u;
            #pragma unroll 4
            for (int j = 0; j < MQ; ++j) {
                unsigned eq  = sEq[s * PADW + j];
                unsigned xv  = eq | mv;
                unsigned xh  = (((eq & pv) + pv) ^ pv) | eq;
                unsigned ph  = mv | ~(xh | pv);
                unsigned mh  = pv & xh;
                unsigned phs = (ph << 1) | 1u;
                unsigned mhs = mh << 1;
                unsigned pv2 = mhs | ~(xv | phs);
                unsigned mv2 = phs & xv;
                unsigned dg = eq | (pv2 & ~phs & ~mhs) | (~pv2 & ~mv2 & phs);
                sDg[s * PADW + j] = dg;
                sUp[s * PADW + j] = pv2 & ~dg;
                pv = pv2; mv = mv2;
            }
            int ii = LQ, jj = MQ, n = 0;
            unsigned dg = sDg[s * PADW + jj - 1];
            unsigned up = sUp[s * PADW + jj - 1];
            while ((ii | jj) != 0) {
                int code;
                if (ii > 0 && jj > 0) {
                    unsigned bit = 1u << (ii - 1);
                    code = (dg & bit) ? 0 : ((up & bit) ? 1 : 2);
                } else code = (ii > 0) ? 1 : 2;
                if (code == 0) {
                    sPair[s * PADW + n] =
                        (unsigned)(ii - 1) | ((unsigned)(jj - 1) << 6);
                    ++n; --ii; --jj;
                    if (jj > 0) { dg = sDg[s*PADW+jj-1]; up = sUp[s*PADW+jj-1]; }
                } else if (code == 1) { --ii; }
                else { --jj;
                    if (jj > 0) { dg = sDg[s*PADW+jj-1]; up = sUp[s*PADW+jj-1]; }
                }
            }
            sN[s] = n;
        }
    }
    __syncthreads();

    // ================= Phase 4: CE over diagonal steps =====================
    if (act) {
        int n = sN[warp];
        unsigned pr = sPair[warp * PADW + ((lane < n) ? lane : 0)];
        int xi = pr & 31;
        int yj = (pr >> 6) & 31;
        int lab = __shfl_sync(FULL, t_reg, yj);
        float lsev = __shfl_sync(FULL, my_lse, xi);
        float ce = 0.f;
        if (lane < n)
            ce = lsev - __ldg(x + (size_t)b * (LQ * CQ) + xi * CQ + lab);
        #pragma unroll
        for (int o = 16; o; o >>= 1) ce += __shfl_xor_sync(FULL, ce, o);
        if (lane == 0)
            g_pn[b] = make_float2((n > 0) ? ce / (float)n : 0.f,
                                  (n > 0) ? 1.f : 0.f);
    }

    // ================= fused final reduction (last block) ==================
    __syncthreads();
    if (threadIdx.x == 0) {
        __threadfence();
        unsigned t = atomicAdd(&g_done, 1u);
        s_last = (t == (unsigned)(nblocks - 1)) ? 1u : 0u;
    }
    __syncthreads();
    if (s_last) {
        __threadfence();
        const float4* p = (const float4*)g_pn;
        float s = 0.f, c = 0.f;
        int n4 = B >> 1;
        for (int idx = threadIdx.x; idx < n4; idx += 32 * SPB) {
            float4 v = p[idx];
            s += v.x + v.z;
            c += v.y + v.w;
        }
        if ((B & 1) && threadIdx.x == 0) { float2 t2 = g_pn[B-1]; s += t2.x; c += t2.y; }
        ss[threadIdx.x] = s; sc[threadIdx.x] = c;
        __syncthreads();
        #pragma unroll
        for (int o = 16 * SPB; o > 0; o >>= 1) {
            if ((int)threadIdx.x < o) {
                ss[threadIdx.x] += ss[threadIdx.x + o];
                sc[threadIdx.x] += sc[threadIdx.x + o];
            }
            __syncthreads();
        }
        if (threadIdx.x == 0) {
            out[0] = ss[0] / sc[0];
            g_done = 0;
        }
    }
}

extern "C" void kernel_launch(void* const* d_in, const int* in_sizes, int n_in,
                              void* d_out, int out_size)
{
    const float* x = (const float*)d_in[0];
    const int*   y = (const int*)d_in[1];
    int B = in_sizes[2];
    if (B > MAXB) B = MAXB;

    int blocks = (B + SPB - 1) / SPB;
    editloss_main<<<blocks, 32 * SPB>>>(x, y, (float*)d_out, B, blocks);
}

// round 17
// speedup vs baseline: 1.1704x; 1.0420x over previous
#include <cuda_runtime.h>
#include <cstdint>

#define FULL 0xFFFFFFFFu
#define LQ 32
#define MQ 32
#define CQ 96
#define SPB 8
#define PADW 33
#define MAXB 8192

__device__ float2 g_pn[MAXB];
__device__ unsigned g_done;

__device__ __forceinline__ unsigned forder(float f) {
    unsigned u = __float_as_uint(f);
    return u ^ (unsigned)(((int)u >> 31) | 0x80000000);
}
__device__ __forceinline__ float ex2(float a) {
    float r; asm("ex2.approx.f32 %0, %1;" : "=f"(r) : "f"(a)); return r;
}

__global__ void __launch_bounds__(32 * SPB, 5) editloss_main(
    const float* __restrict__ x, const int* __restrict__ y,
    float* __restrict__ out, int B, int nblocks)
{
    __shared__ unsigned sEq[SPB * PADW];
    __shared__ unsigned sDg[SPB * PADW];
    __shared__ unsigned sUp[SPB * PADW];
    __shared__ unsigned sPair[SPB * PADW];
    __shared__ int      sN[SPB];
    __shared__ float    ss[32 * SPB], sc[32 * SPB];
    __shared__ unsigned s_last;

    const int warp = threadIdx.x >> 5;
    const int lane = threadIdx.x & 31;
    const int b = blockIdx.x * SPB + warp;
    const bool act = (b < B);

    float my_lse = 0.f; int my_pred = 0; int t_reg = 0;

    // ================= Phase 1: softmax/argmax + Eq masks ==================
    if (act) {
        const float4* xb4 = (const float4*)(x + (size_t)b * (LQ * CQ));
        t_reg = y[b * MQ + lane];
        const int ibase = 4 * lane;
        int my_stot = 1;   // guards log(0); real rows always overwrite

        #pragma unroll 4
        for (int r = 0; r < LQ; ++r) {
            float4 v = (lane < 24) ? xb4[r * 24 + lane]
                                   : make_float4(-1e30f, -1e30f, -1e30f, -1e30f);
            float m = v.x; int idx = ibase;
            if (v.y > m) { m = v.y; idx = ibase + 1; }
            if (v.z > m) { m = v.z; idx = ibase + 2; }
            if (v.w > m) { m = v.w; idx = ibase + 3; }
            unsigned fo = forder(m);
            unsigned wmax = __reduce_max_sync(FULL, fo);
            unsigned cand = (fo == wmax) ? (unsigned)idx : 1023u;
            int widx = (int)__reduce_min_sync(FULL, cand);
            // sum of exp(v)*2^14 via ex2(v*log2e + 14), fixed-point warp add
            float e0 = ex2(fmaf(v.x, 1.44269504f, 14.f));
            float e1 = ex2(fmaf(v.y, 1.44269504f, 14.f));
            float e2 = ex2(fmaf(v.z, 1.44269504f, 14.f));
            float e3 = ex2(fmaf(v.w, 1.44269504f, 14.f));
            int si = __float2int_rn((e0 + e1) + (e2 + e3));
            int stot = __reduce_add_sync(FULL, si);
            if (lane == r) { my_pred = widx; my_stot = stot; }
        }
        // log once, outside the row loop
        my_lse = __logf((float)my_stot) - 14.f * 0.69314718f;

        // match mask: lane = row r, bit j = (pred_r == tgt_j)
        unsigned mmask = 0;
        #pragma unroll
        for (int o = 0; o < MQ; ++o) {
            int tc = __shfl_sync(FULL, t_reg, o);
            if (my_pred == tc) mmask |= 1u << o;
        }
        // warp 32x32 bit transpose -> lane j holds Eq_j (bits over rows)
        unsigned w = mmask;
        {
            unsigned yv;
            yv = __shfl_xor_sync(FULL, w, 16);
            w = (lane & 16) ? ((w & 0xFFFF0000u) | ((yv >> 16) & 0x0000FFFFu))
                            : ((w & 0x0000FFFFu) | ((yv & 0x0000FFFFu) << 16));
            yv = __shfl_xor_sync(FULL, w, 8);
            w = (lane & 8) ? ((w & 0xFF00FF00u) | ((yv >> 8) & 0x00FF00FFu))
                           : ((w & 0x00FF00FFu) | ((yv & 0x00FF00FFu) << 8));
            yv = __shfl_xor_sync(FULL, w, 4);
            w = (lane & 4) ? ((w & 0xF0F0F0F0u) | ((yv >> 4) & 0x0F0F0F0Fu))
                           : ((w & 0x0F0F0F0Fu) | ((yv & 0x0F0F0F0Fu) << 4));
            yv = __shfl_xor_sync(FULL, w, 2);
            w = (lane & 2) ? ((w & 0xCCCCCCCCu) | ((yv >> 2) & 0x33333333u))
                           : ((w & 0x33333333u) | ((yv & 0x33333333u) << 2));
            yv = __shfl_xor_sync(FULL, w, 1);
            w = (lane & 1) ? ((w & 0xAAAAAAAAu) | ((yv >> 1) & 0x55555555u))
                           : ((w & 0x55555555u) | ((yv & 0x55555555u) << 1));
        }
        sEq[warp * PADW + lane] = w;
    }
    __syncthreads();

    // ============ Phase 2+3: Myers bit-parallel DP + backtrace =============
    if (threadIdx.x < SPB) {
        const int s = threadIdx.x;
        if (blockIdx.x * SPB + s < B) {
            unsigned pv = 0xFFFFFFFFu, mv = 0u;
            #pragma unroll 4
            for (int j = 0; j < MQ; ++j) {
                unsigned eq  = sEq[s * PADW + j];
                unsigned xv  = eq | mv;
                unsigned xh  = (((eq & pv) + pv) ^ pv) | eq;
                unsigned ph  = mv | ~(xh | pv);
                unsigned mh  = pv & xh;
                unsigned phs = (ph << 1) | 1u;
                unsigned mhs = mh << 1;
                unsigned pv2 = mhs | ~(xv | phs);
                unsigned mv2 = phs & xv;
                unsigned dg = eq | (pv2 & ~phs & ~mhs) | (~pv2 & ~mv2 & phs);
                sDg[s * PADW + j] = dg;
                sUp[s * PADW + j] = pv2 & ~dg;
                pv = pv2; mv = mv2;
            }
            int ii = LQ, jj = MQ, n = 0;
            unsigned dg = sDg[s * PADW + jj - 1];
            unsigned up = sUp[s * PADW + jj - 1];
            while ((ii | jj) != 0) {
                int code;
                if (ii > 0 && jj > 0) {
                    unsigned bit = 1u << (ii - 1);
                    code = (dg & bit) ? 0 : ((up & bit) ? 1 : 2);
                } else code = (ii > 0) ? 1 : 2;
                if (code == 0) {
                    sPair[s * PADW + n] =
                        (unsigned)(ii - 1) | ((unsigned)(jj - 1) << 6);
                    ++n; --ii; --jj;
                    if (jj > 0) { dg = sDg[s*PADW+jj-1]; up = sUp[s*PADW+jj-1]; }
                } else if (code == 1) { --ii; }
                else { --jj;
                    if (jj > 0) { dg = sDg[s*PADW+jj-1]; up = sUp[s*PADW+jj-1]; }
                }
            }
            sN[s] = n;
        }
    }
    __syncthreads();

    // ================= Phase 4: CE over diagonal steps =====================
    if (act) {
        int n = sN[warp];
        unsigned pr = sPair[warp * PADW + ((lane < n) ? lane : 0)];
        int xi = pr & 31;
        int yj = (pr >> 6) & 31;
        int lab = __shfl_sync(FULL, t_reg, yj);
        float lsev = __shfl_sync(FULL, my_lse, xi);
        float ce = 0.f;
        if (lane < n)
            ce = lsev - __ldg(x + (size_t)b * (LQ * CQ) + xi * CQ + lab);
        #pragma unroll
        for (int o = 16; o; o >>= 1) ce += __shfl_xor_sync(FULL, ce, o);
        if (lane == 0)
            g_pn[b] = make_float2((n > 0) ? ce / (float)n : 0.f,
                                  (n > 0) ? 1.f : 0.f);
    }

    // ================= fused final reduction (last block) ==================
    __syncthreads();
    if (threadIdx.x == 0) {
        __threadfence();
        unsigned t = atomicAdd(&g_done, 1u);
        s_last = (t == (unsigned)(nblocks - 1)) ? 1u : 0u;
    }
    __syncthreads();
    if (s_last) {
        __threadfence();
        const float4* p = (const float4*)g_pn;
        float s = 0.f, c = 0.f;
        int n4 = B >> 1;
        for (int idx = threadIdx.x; idx < n4; idx += 32 * SPB) {
            float4 v = p[idx];
            s += v.x + v.z;
            c += v.y + v.w;
        }
        if ((B & 1) && threadIdx.x == 0) { float2 t2 = g_pn[B-1]; s += t2.x; c += t2.y; }
        ss[threadIdx.x] = s; sc[threadIdx.x] = c;
        __syncthreads();
        #pragma unroll
        for (int o = 16 * SPB; o > 0; o >>= 1) {
            if ((int)threadIdx.x < o) {
                ss[threadIdx.x] += ss[threadIdx.x + o];
                sc[threadIdx.x] += sc[threadIdx.x + o];
            }
            __syncthreads();
        }
        if (threadIdx.x == 0) {
            out[0] = ss[0] / sc[0];
            g_done = 0;
        }
    }
}

extern "C" void kernel_launch(void* const* d_in, const int* in_sizes, int n_in,
                              void* d_out, int out_size)
{
    const float* x = (const float*)d_in[0];
    const int*   y = (const int*)d_in[1];
    int B = in_sizes[2];
    if (B > MAXB) B = MAXB;

    int blocks = (B + SPB - 1) / SPB;
    editloss_main<<<blocks, 32 * SPB>>>(x, y, (float*)d_out, B, blocks);
}